// round 7
// baseline (speedup 1.0000x reference)
#include <cuda_runtime.h>
#include <cuda_fp16.h>
#include <cstdint>

// Problem dims
#define BB 128
#define TT 512
#define II 256
#define HH 512
#define KK 768               // I + H
#define CLU 16

// ---------------- device-global scratch ----------------
__device__ __half g_P[(size_t)BB * TT * 2048];   // preact x·Wx^T + bias, [m=b*512+t][gc]
__device__ uint4  g_WhF2[16 * 8 * 32 * 32];      // 2 MB : Wh B-frags
__device__ uint2  g_WxF[256 * 16 * 32];          // 1 MB : Wx B-frags (global n8-tiles)
__device__ uint4  g_hf[2 * 8 * 1024];            // h in A-frag order, double buffered

// ---------------- helpers ----------------
__device__ __forceinline__ uint32_t smem_u32(const void* p) {
    uint32_t a;
    asm("{ .reg .u64 t; cvta.to.shared.u64 t, %1; cvt.u32.u64 %0, t; }" : "=r"(a) : "l"(p));
    return a;
}
__device__ __forceinline__ uint4 ldcg_v4(const uint4* p) {
    uint4 v;
    asm volatile("ld.global.cg.v4.u32 {%0,%1,%2,%3}, [%4];"
                 : "=r"(v.x), "=r"(v.y), "=r"(v.z), "=r"(v.w) : "l"(p));
    return v;
}
__device__ __forceinline__ void mma16816(float* c, const uint4& a, unsigned b0, unsigned b1) {
    asm volatile(
        "mma.sync.aligned.m16n8k16.row.col.f32.f16.f16.f32 "
        "{%0,%1,%2,%3}, {%4,%5,%6,%7}, {%8,%9}, {%0,%1,%2,%3};"
        : "+f"(c[0]), "+f"(c[1]), "+f"(c[2]), "+f"(c[3])
        : "r"(a.x), "r"(a.y), "r"(a.z), "r"(a.w), "r"(b0), "r"(b1));
}
__device__ __forceinline__ void ldmatrix_x4(uint4& a, uint32_t addr) {
    asm volatile("ldmatrix.sync.aligned.m8n8.x4.shared.b16 {%0,%1,%2,%3}, [%4];"
                 : "=r"(a.x), "=r"(a.y), "=r"(a.z), "=r"(a.w) : "r"(addr));
}
__device__ __forceinline__ float sigf(float x) {
    return __fdividef(1.0f, 1.0f + __expf(-x));
}
__device__ __forceinline__ float tanh_fast(float x) {
    float e = __expf(2.0f * x);
    return 1.0f - __fdividef(2.0f, e + 1.0f);
}

// ---------------- pack kernel (unchanged) ----------------
__global__ __launch_bounds__(256) void pack_kernel(
    const float* __restrict__ Wf, const float* __restrict__ Wu,
    const float* __restrict__ Wc, const float* __restrict__ Wo) {
    int gid = blockIdx.x * 256 + threadIdx.x;
    if (blockIdx.x < 512) {
        int lane = gid & 31, kt = (gid >> 5) & 31, w = (gid >> 10) & 7, r = (gid >> 13) & 15;
        int gsel = (lane >> 2) & 1;
        int cell = r * 32 + w * 4 + (lane >> 3);
        unsigned* dst = reinterpret_cast<unsigned*>(g_WhF2);
        unsigned base = ((((unsigned)(r * 8 + w) * 32 + kt) * 32 + lane)) * 4;
        #pragma unroll
        for (int q = 0; q < 4; q++) {
            int gate = (q >> 1) * 2 + gsel;
            const float* W = (gate == 0) ? Wf : (gate == 1) ? Wu : (gate == 2) ? Wc : Wo;
            int k2 = (lane & 3) + 4 * (q & 1);
            int kcol = 256 + kt * 16 + k2 * 2;
            __half2 hv = __floats2half2_rn(W[(size_t)cell * KK + kcol],
                                           W[(size_t)cell * KK + kcol + 1]);
            dst[base + q] = *reinterpret_cast<unsigned*>(&hv);
        }
    } else {
        int gid2 = gid - 512 * 256;
        int kt = gid2 & 15, gc = gid2 >> 4;
        int gate = gc >> 9;
        const float* W = (gate == 0) ? Wf : (gate == 1) ? Wu : (gate == 2) ? Wc : Wo;
        const float4* src = reinterpret_cast<const float4*>(W + (size_t)(gc & 511) * KK + kt * 16);
        float4 v0 = src[0], v1 = src[1], v2 = src[2], v3 = src[3];
        float vv[16] = {v0.x, v0.y, v0.z, v0.w, v1.x, v1.y, v1.z, v1.w,
                        v2.x, v2.y, v2.z, v2.w, v3.x, v3.y, v3.z, v3.w};
        unsigned* dst = reinterpret_cast<unsigned*>(g_WxF);
        unsigned base = (((unsigned)(gc >> 3) * 16 + kt) * 32) * 2;
        #pragma unroll
        for (int k2 = 0; k2 < 8; k2++) {
            int lane = (gc & 7) * 4 + (k2 & 3);
            int reg = k2 >> 2;
            __half2 hv = __floats2half2_rn(vv[2 * k2], vv[2 * k2 + 1]);
            dst[base + lane * 2 + reg] = *reinterpret_cast<unsigned*>(&hv);
        }
    }
}

// ---------------- prologue GEMM: P = x·Wx^T + bias (unchanged) ----------------
#define GM_SMEM (128 * 264 * 2)

__global__ __launch_bounds__(256) void gemm_kernel(
    const float* __restrict__ x,
    const float* __restrict__ bf, const float* __restrict__ bu,
    const float* __restrict__ bc, const float* __restrict__ bo) {
    extern __shared__ char smem[];
    __half* As = reinterpret_cast<__half*>(smem);
    const int tid = threadIdx.x;
    const int w = tid >> 5, l = tid & 31;
    const int nb = blockIdx.x, mb = blockIdx.y;

    {
        unsigned* As32 = reinterpret_cast<unsigned*>(As);
        #pragma unroll 4
        for (int i = 0; i < 32; i++) {
            int idx = tid + i * 256;
            int row = idx >> 6, c4 = idx & 63;
            float4 v = *reinterpret_cast<const float4*>(&x[((size_t)mb * 128 + row) * 256 + c4 * 4]);
            __half2 h0 = __floats2half2_rn(v.x, v.y);
            __half2 h1 = __floats2half2_rn(v.z, v.w);
            As32[row * 132 + c4 * 2]     = *reinterpret_cast<unsigned*>(&h0);
            As32[row * 132 + c4 * 2 + 1] = *reinterpret_cast<unsigned*>(&h1);
        }
    }
    __syncthreads();

    const int gate = nb >> 2;
    const float* bias = (gate == 0) ? bf : (gate == 1) ? bu : (gate == 2) ? bc : bo;
    float bcol[4][2];
    #pragma unroll
    for (int nt = 0; nt < 4; nt++) {
        int cb = (nb & 3) * 128 + (w & 3) * 32 + nt * 8 + (l & 3) * 2;
        bcol[nt][0] = bias[cb];
        bcol[nt][1] = bias[cb + 1];
    }

    float acc[4][4][4];
    #pragma unroll
    for (int a = 0; a < 4; a++)
        #pragma unroll
        for (int b = 0; b < 4; b++)
            #pragma unroll
            for (int c = 0; c < 4; c++) acc[a][b][c] = 0.f;

    const uint2* Bbase = g_WxF + (size_t)(nb * 16 + (w & 3) * 4) * 16 * 32;
    const uint32_t a_s = smem_u32(As);
    const int mrow0 = (w >> 2) * 64;
    const int m = l >> 3;

    #pragma unroll 2
    for (int kt = 0; kt < 16; kt++) {
        uint2 bfr[4];
        #pragma unroll
        for (int nt = 0; nt < 4; nt++) bfr[nt] = Bbase[(nt * 16 + kt) * 32 + l];
        uint4 afr[4];
        #pragma unroll
        for (int mt = 0; mt < 4; mt++) {
            uint32_t addr = a_s +
                ((mrow0 + mt * 16 + (m & 1) * 8 + (l & 7)) * 264 + kt * 16 + (m >> 1) * 8) * 2;
            ldmatrix_x4(afr[mt], addr);
        }
        #pragma unroll
        for (int mt = 0; mt < 4; mt++)
            #pragma unroll
            for (int nt = 0; nt < 4; nt++)
                mma16816(acc[mt][nt], afr[mt], bfr[nt].x, bfr[nt].y);
    }

    #pragma unroll
    for (int mt = 0; mt < 4; mt++) {
        #pragma unroll
        for (int nt = 0; nt < 4; nt++) {
            int mloc = mrow0 + mt * 16 + (l >> 2);
            size_t m0 = (size_t)mb * 128 + mloc;
            int gc = nb * 128 + (w & 3) * 32 + nt * 8 + (l & 3) * 2;
            #pragma unroll
            for (int cp = 0; cp < 2; cp++) {
                float v0 = acc[mt][nt][cp * 2]     + bcol[nt][0];
                float v1 = acc[mt][nt][cp * 2 + 1] + bcol[nt][1];
                __half2 hv = __floats2half2_rn(v0, v1);
                *reinterpret_cast<unsigned*>(&g_P[(m0 + cp * 8) * 2048 + gc]) =
                    *reinterpret_cast<unsigned*>(&hv);
            }
        }
    }
}

// ---------------- recurrent kernel ----------------
// 8 clusters x 16 CTAs; 512 threads = 16 warps (4/SMSP for bubble-filling).
// N-split: warps 0-7 compute gates f/u for cells w*4..w*4+3; warps 8-15 the
// same cells' gates c/o. Upper warps hand their preacts to partners via SMEM;
// lower warps run the epilogue. Weights in registers (32 uint2/thread).
#define L_SMEM (16384 + 4096)

__global__ void __cluster_dims__(CLU, 1, 1) __launch_bounds__(512, 1)
lstm_kernel(float* __restrict__ out) {
    extern __shared__ char smem[];
    uint4* sA = reinterpret_cast<uint4*>(smem);                  // 1024 uint4 = h A-frags
    float* sX = reinterpret_cast<float*>(smem + 16384);          // 4 x 256 floats exchange

    const int tid  = threadIdx.x;
    const int w    = tid >> 5;
    const int lane = tid & 31;
    const int wl   = w & 7;               // logical warp (cell group)
    const int up   = w >> 3;              // 0 = gates f/u, 1 = gates c/o
    const int r    = blockIdx.x & (CLU - 1);
    const int bgrp = blockIdx.x >> 4;
    const int bb   = bgrp * 16;
    const int hb   = r * 32;

    // ---- weights into registers (once): this warp's single n8-tile ----
    uint2 wb_[32];
    {
        const uint2* src = reinterpret_cast<const uint2*>(g_WhF2);
        size_t base = (((size_t)(r * 8 + wl) * 32) * 32 + lane) * 2 + up;
        #pragma unroll
        for (int kt = 0; kt < 32; kt++) wb_[kt] = src[base + (size_t)kt * 64];
    }

    // ---- per-thread ownership: rows {rA, rA+8}, cell hg, gate pair 'up' ----
    const int rA = lane >> 2;
    const int hg = hb + wl * 4 + (lane & 3);
    const int goff = up * 1024;           // P gate offset: 0 -> f/u, 1024 -> c/o

    float cs0 = 0.f, cs1 = 0.f, hv0 = 0.f, hv1 = 0.f;

    const __half* P0 = g_P + ((size_t)(bb + rA) * 512) * 2048;
    const __half* P8 = g_P + ((size_t)(bb + rA + 8) * 512) * 2048;
    __half* hf16 = reinterpret_cast<__half*>(g_hf);

    // pv: {gate0@rA, gate1@rA, gate0@rA8, gate1@rA8} for this warp's gate pair
    float pv[4];
    {
        pv[0] = __half2float(__ldg(P0 + goff + hg));
        pv[1] = __half2float(__ldg(P0 + goff + 512 + hg));
        pv[2] = __half2float(__ldg(P8 + goff + hg));
        pv[3] = __half2float(__ldg(P8 + goff + 512 + hg));
    }

    for (int t = 0; t < TT; t++) {
        // ---- stage A frags: h(t) from g_hf (frag order), zeros at t=0 ----
        // Safe: cluster barrier at end of prev iter ensures all MMA reads done.
        if (t == 0) {
            uint4 z = make_uint4(0, 0, 0, 0);
            #pragma unroll
            for (int i = 0; i < 2; i++) sA[tid + i * 512] = z;
        } else {
            const uint4* hf = g_hf + ((size_t)(t & 1) * 8 + bgrp) * 1024;
            #pragma unroll
            for (int i = 0; i < 2; i++) sA[tid + i * 512] = ldcg_v4(hf + tid + i * 512);
        }
        __syncthreads();

        // ---- 2 independent chains, seeded with P(t) ----
        float ae[4] = {pv[0], pv[1], pv[2], pv[3]};
        float ao[4] = {0.f, 0.f, 0.f, 0.f};

        // ---- GEMM: 16 x 128 x 512 (this warp: 16x8), B in registers ----
        #pragma unroll
        for (int kt = 0; kt < 32; kt += 2) {
            uint4 A0 = sA[kt * 32 + lane];
            uint4 A1 = sA[(kt + 1) * 32 + lane];
            mma16816(ae, A0, wb_[kt].x, wb_[kt].y);
            mma16816(ao, A1, wb_[kt + 1].x, wb_[kt + 1].y);
        }
        #pragma unroll
        for (int i = 0; i < 4; i++) ae[i] += ao[i];

        // ---- upper warps hand c/o preacts to partners ----
        if (up) {
            int t8 = tid - 256;
            #pragma unroll
            for (int i = 0; i < 4; i++) sX[i * 256 + t8] = ae[i];
        }
        __syncthreads();

        // ---- lower warps: epilogue for 2 rows of cell hg ----
        if (!up) {
            float p0 = sX[tid], p1 = sX[256 + tid], p2 = sX[512 + tid], p3 = sX[768 + tid];
            float f, u, g, o;
            f = sigf(ae[0]); u = sigf(ae[1]); g = tanh_fast(p0); o = sigf(p1);
            cs0 = f * cs0 + u * g;  hv0 = o * tanh_fast(cs0);
            f = sigf(ae[2]); u = sigf(ae[3]); g = tanh_fast(p2); o = sigf(p3);
            cs1 = f * cs1 + u * g;  hv1 = o * tanh_fast(cs1);

            // publish h(t+1) in A-frag order (must precede release)
            const int wb2 = (t + 1) & 1;
            const int blk = (wb2 * 8 + bgrp) * 1024;
            size_t i0 = ((size_t)(blk + (hg >> 4) * 32 + rA * 4 + ((hg >> 1) & 3))) * 8
                        + (((hg >> 3) & 1) * 2) * 2 + (hg & 1);
            hf16[i0] = __float2half(hv0);
            hf16[i0 + 2] = __float2half(hv1);
        }

        asm volatile("barrier.cluster.arrive.release.aligned;" ::: "memory");

        // ---- under the barrier wait: out stores + P(t+1) prefetch ----
        if (!up) {
            out[(size_t)t * (BB * HH) + (size_t)(bb + rA) * HH + hg] = hv0;
            out[(size_t)t * (BB * HH) + (size_t)(bb + rA + 8) * HH + hg] = hv1;
        }
        if (t + 1 < TT) {
            const __half* p0 = P0 + (size_t)(t + 1) * 2048;
            const __half* p8 = P8 + (size_t)(t + 1) * 2048;
            pv[0] = __half2float(__ldg(p0 + goff + hg));
            pv[1] = __half2float(__ldg(p0 + goff + 512 + hg));
            pv[2] = __half2float(__ldg(p8 + goff + hg));
            pv[3] = __half2float(__ldg(p8 + goff + 512 + hg));
        }

        asm volatile("barrier.cluster.wait.acquire.aligned;" ::: "memory");
    }

    // ---- final h, c (lower warps own the state) ----
    if (!up) {
        const size_t OUT_H = (size_t)TT * BB * HH;
        const size_t OUT_C = OUT_H + (size_t)BB * HH;
        size_t b0 = (size_t)(bb + rA) * HH + hg;
        size_t b1 = (size_t)(bb + rA + 8) * HH + hg;
        out[OUT_H + b0] = hv0;  out[OUT_H + b1] = hv1;
        out[OUT_C + b0] = cs0;  out[OUT_C + b1] = cs1;
    }
}

// ---------------- tail kernel (4th launch: aligns ncu capture on lstm) ----------------
__global__ void tail_kernel() {}

// ---------------- launcher (4 launches) ----------------

extern "C" void kernel_launch(void* const* d_in, const int* in_sizes, int n_in,
                              void* d_out, int out_size) {
    (void)in_sizes; (void)n_in; (void)out_size;
    const float* x  = (const float*)d_in[0];
    const float* Wf = (const float*)d_in[1];
    const float* bf = (const float*)d_in[2];
    const float* Wu = (const float*)d_in[3];
    const float* bu = (const float*)d_in[4];
    const float* Wc = (const float*)d_in[5];
    const float* bc = (const float*)d_in[6];
    const float* Wo = (const float*)d_in[7];
    const float* bo = (const float*)d_in[8];
    float* out = (float*)d_out;

    cudaFuncSetAttribute(gemm_kernel, cudaFuncAttributeMaxDynamicSharedMemorySize, GM_SMEM);
    cudaFuncSetAttribute(lstm_kernel, cudaFuncAttributeMaxDynamicSharedMemorySize, L_SMEM);
    cudaFuncSetAttribute(lstm_kernel, cudaFuncAttributeNonPortableClusterSizeAllowed, 1);

    pack_kernel<<<640, 256>>>(Wf, Wu, Wc, Wo);
    gemm_kernel<<<dim3(16, 512), 256, GM_SMEM>>>(x, bf, bu, bc, bo);
    lstm_kernel<<<BB, 512, L_SMEM>>>(out);
    tail_kernel<<<1, 32>>>();
}

// round 9
// speedup vs baseline: 1.1600x; 1.1600x over previous
#include <cuda_runtime.h>
#include <cuda_fp16.h>
#include <cstdint>

// Problem dims
#define BB 128
#define TT 512
#define II 256
#define HH 512
#define KK 768               // I + H
#define CLU 16

// ---------------- device-global scratch ----------------
__device__ __half g_P[(size_t)BB * TT * 2048];   // preact x·Wx^T + bias, [m=b*512+t][gc]
__device__ uint4  g_WhF2[16 * 8 * 32 * 32];      // 2 MB : Wh B-frags
__device__ uint2  g_WxF[256 * 16 * 32];          // 1 MB : Wx B-frags (global n8-tiles)
__device__ uint4  g_hf[2 * 8 * 1024];            // h in A-frag order, double buffered

// ---------------- helpers ----------------
__device__ __forceinline__ uint32_t smem_u32(const void* p) {
    uint32_t a;
    asm("{ .reg .u64 t; cvta.to.shared.u64 t, %1; cvt.u32.u64 %0, t; }" : "=r"(a) : "l"(p));
    return a;
}
__device__ __forceinline__ uint4 ldcg_v4(const uint4* p) {
    uint4 v;
    asm volatile("ld.global.cg.v4.u32 {%0,%1,%2,%3}, [%4];"
                 : "=r"(v.x), "=r"(v.y), "=r"(v.z), "=r"(v.w) : "l"(p));
    return v;
}
__device__ __forceinline__ void mma16816(float* c, const uint4& a, unsigned b0, unsigned b1) {
    asm volatile(
        "mma.sync.aligned.m16n8k16.row.col.f32.f16.f16.f32 "
        "{%0,%1,%2,%3}, {%4,%5,%6,%7}, {%8,%9}, {%0,%1,%2,%3};"
        : "+f"(c[0]), "+f"(c[1]), "+f"(c[2]), "+f"(c[3])
        : "r"(a.x), "r"(a.y), "r"(a.z), "r"(a.w), "r"(b0), "r"(b1));
}
// f16-accumulate variant: D/C are 2 b32 regs = 4 halves per thread
__device__ __forceinline__ void mma16816_f16(unsigned* c, const uint4& a, unsigned b0, unsigned b1) {
    asm volatile(
        "mma.sync.aligned.m16n8k16.row.col.f16.f16.f16.f16 "
        "{%0,%1}, {%2,%3,%4,%5}, {%6,%7}, {%0,%1};"
        : "+r"(c[0]), "+r"(c[1])
        : "r"(a.x), "r"(a.y), "r"(a.z), "r"(a.w), "r"(b0), "r"(b1));
}
__device__ __forceinline__ void ldmatrix_x4(uint4& a, uint32_t addr) {
    asm volatile("ldmatrix.sync.aligned.m8n8.x4.shared.b16 {%0,%1,%2,%3}, [%4];"
                 : "=r"(a.x), "=r"(a.y), "=r"(a.z), "=r"(a.w) : "r"(addr));
}
__device__ __forceinline__ float sigf(float x) {
    return __fdividef(1.0f, 1.0f + __expf(-x));
}
__device__ __forceinline__ float tanh_fast(float x) {
    float e = __expf(2.0f * x);
    return 1.0f - __fdividef(2.0f, e + 1.0f);
}

// ---------------- pack kernel (unchanged) ----------------
__global__ __launch_bounds__(256) void pack_kernel(
    const float* __restrict__ Wf, const float* __restrict__ Wu,
    const float* __restrict__ Wc, const float* __restrict__ Wo) {
    int gid = blockIdx.x * 256 + threadIdx.x;
    if (blockIdx.x < 512) {
        int lane = gid & 31, kt = (gid >> 5) & 31, w = (gid >> 10) & 7, r = (gid >> 13) & 15;
        int gsel = (lane >> 2) & 1;
        int cell = r * 32 + w * 4 + (lane >> 3);
        unsigned* dst = reinterpret_cast<unsigned*>(g_WhF2);
        unsigned base = ((((unsigned)(r * 8 + w) * 32 + kt) * 32 + lane)) * 4;
        #pragma unroll
        for (int q = 0; q < 4; q++) {
            int gate = (q >> 1) * 2 + gsel;
            const float* W = (gate == 0) ? Wf : (gate == 1) ? Wu : (gate == 2) ? Wc : Wo;
            int k2 = (lane & 3) + 4 * (q & 1);
            int kcol = 256 + kt * 16 + k2 * 2;
            __half2 hv = __floats2half2_rn(W[(size_t)cell * KK + kcol],
                                           W[(size_t)cell * KK + kcol + 1]);
            dst[base + q] = *reinterpret_cast<unsigned*>(&hv);
        }
    } else {
        int gid2 = gid - 512 * 256;
        int kt = gid2 & 15, gc = gid2 >> 4;
        int gate = gc >> 9;
        const float* W = (gate == 0) ? Wf : (gate == 1) ? Wu : (gate == 2) ? Wc : Wo;
        const float4* src = reinterpret_cast<const float4*>(W + (size_t)(gc & 511) * KK + kt * 16);
        float4 v0 = src[0], v1 = src[1], v2 = src[2], v3 = src[3];
        float vv[16] = {v0.x, v0.y, v0.z, v0.w, v1.x, v1.y, v1.z, v1.w,
                        v2.x, v2.y, v2.z, v2.w, v3.x, v3.y, v3.z, v3.w};
        unsigned* dst = reinterpret_cast<unsigned*>(g_WxF);
        unsigned base = (((unsigned)(gc >> 3) * 16 + kt) * 32) * 2;
        #pragma unroll
        for (int k2 = 0; k2 < 8; k2++) {
            int lane = (gc & 7) * 4 + (k2 & 3);
            int reg = k2 >> 2;
            __half2 hv = __floats2half2_rn(vv[2 * k2], vv[2 * k2 + 1]);
            dst[base + lane * 2 + reg] = *reinterpret_cast<unsigned*>(&hv);
        }
    }
}

// ---------------- prologue GEMM: P = x·Wx^T + bias (f16 accumulate) ----------------
// Two independent f16 chains (even/odd kt, depth 8 each), merged + bias in half2.
#define GM_SMEM (128 * 264 * 2)

__global__ __launch_bounds__(256) void gemm_kernel(
    const float* __restrict__ x,
    const float* __restrict__ bf, const float* __restrict__ bu,
    const float* __restrict__ bc, const float* __restrict__ bo) {
    extern __shared__ char smem[];
    __half* As = reinterpret_cast<__half*>(smem);
    const int tid = threadIdx.x;
    const int w = tid >> 5, l = tid & 31;
    const int nb = blockIdx.x, mb = blockIdx.y;

    {
        unsigned* As32 = reinterpret_cast<unsigned*>(As);
        #pragma unroll 4
        for (int i = 0; i < 32; i++) {
            int idx = tid + i * 256;
            int row = idx >> 6, c4 = idx & 63;
            float4 v = *reinterpret_cast<const float4*>(&x[((size_t)mb * 128 + row) * 256 + c4 * 4]);
            __half2 h0 = __floats2half2_rn(v.x, v.y);
            __half2 h1 = __floats2half2_rn(v.z, v.w);
            As32[row * 132 + c4 * 2]     = *reinterpret_cast<unsigned*>(&h0);
            As32[row * 132 + c4 * 2 + 1] = *reinterpret_cast<unsigned*>(&h1);
        }
    }
    __syncthreads();

    const int gate = nb >> 2;
    const float* bias = (gate == 0) ? bf : (gate == 1) ? bu : (gate == 2) ? bc : bo;
    unsigned bh[4];                     // half2 bias per n-tile
    #pragma unroll
    for (int nt = 0; nt < 4; nt++) {
        int cb = (nb & 3) * 128 + (w & 3) * 32 + nt * 8 + (l & 3) * 2;
        __half2 b2 = __floats2half2_rn(bias[cb], bias[cb + 1]);
        bh[nt] = *reinterpret_cast<unsigned*>(&b2);
    }

    unsigned acc_e[4][4][2], acc_o[4][4][2];
    #pragma unroll
    for (int a = 0; a < 4; a++)
        #pragma unroll
        for (int b = 0; b < 4; b++) {
            acc_e[a][b][0] = 0u; acc_e[a][b][1] = 0u;
            acc_o[a][b][0] = 0u; acc_o[a][b][1] = 0u;
        }

    const uint2* Bbase = g_WxF + (size_t)(nb * 16 + (w & 3) * 4) * 16 * 32;
    const uint32_t a_s = smem_u32(As);
    const int mrow0 = (w >> 2) * 64;
    const int m = l >> 3;

    #pragma unroll 2
    for (int kt = 0; kt < 16; kt++) {
        uint2 bfr[4];
        #pragma unroll
        for (int nt = 0; nt < 4; nt++) bfr[nt] = Bbase[(nt * 16 + kt) * 32 + l];
        uint4 afr[4];
        #pragma unroll
        for (int mt = 0; mt < 4; mt++) {
            uint32_t addr = a_s +
                ((mrow0 + mt * 16 + (m & 1) * 8 + (l & 7)) * 264 + kt * 16 + (m >> 1) * 8) * 2;
            ldmatrix_x4(afr[mt], addr);
        }
        if (kt & 1) {
            #pragma unroll
            for (int mt = 0; mt < 4; mt++)
                #pragma unroll
                for (int nt = 0; nt < 4; nt++)
                    mma16816_f16(acc_o[mt][nt], afr[mt], bfr[nt].x, bfr[nt].y);
        } else {
            #pragma unroll
            for (int mt = 0; mt < 4; mt++)
                #pragma unroll
                for (int nt = 0; nt < 4; nt++)
                    mma16816_f16(acc_e[mt][nt], afr[mt], bfr[nt].x, bfr[nt].y);
        }
    }

    // epilogue: merge chains + bias (half2), store to P
    #pragma unroll
    for (int mt = 0; mt < 4; mt++) {
        #pragma unroll
        for (int nt = 0; nt < 4; nt++) {
            int mloc = mrow0 + mt * 16 + (l >> 2);
            size_t m0 = (size_t)mb * 128 + mloc;
            int gc = nb * 128 + (w & 3) * 32 + nt * 8 + (l & 3) * 2;
            __half2 bb2 = *reinterpret_cast<__half2*>(&bh[nt]);
            #pragma unroll
            for (int cp = 0; cp < 2; cp++) {
                __half2 e = *reinterpret_cast<__half2*>(&acc_e[mt][nt][cp]);
                __half2 o = *reinterpret_cast<__half2*>(&acc_o[mt][nt][cp]);
                __half2 s = __hadd2(__hadd2(e, o), bb2);
                *reinterpret_cast<unsigned*>(&g_P[(m0 + cp * 8) * 2048 + gc]) =
                    *reinterpret_cast<unsigned*>(&s);
            }
        }
    }
}

// ---------------- recurrent kernel (R6 proven version) ----------------
#define L_SMEM 16384

__global__ void __cluster_dims__(CLU, 1, 1) __launch_bounds__(256, 1)
lstm_kernel(float* __restrict__ out) {
    extern __shared__ char smem[];
    uint4* sA = reinterpret_cast<uint4*>(smem);       // 1024 uint4 = h A-frags

    const int tid  = threadIdx.x;
    const int w    = tid >> 5;
    const int lane = tid & 31;
    const int r    = blockIdx.x & (CLU - 1);
    const int bgrp = blockIdx.x >> 4;
    const int bb   = bgrp * 16;
    const int hb   = r * 32;

    // ---- weights into registers (once) ----
    uint4 wb_[32];
    {
        const uint4* src = g_WhF2 + ((size_t)(r * 8 + w) * 32) * 32;
        #pragma unroll
        for (int kt = 0; kt < 32; kt++) wb_[kt] = src[kt * 32 + lane];
    }

    // ---- per-thread ownership: rows {rA, rA+8}, cell hg ----
    const int rA = lane >> 2;
    const int hg = hb + w * 4 + (lane & 3);

    float cs0 = 0.f, cs1 = 0.f, hv0 = 0.f, hv1 = 0.f;

    const __half* P0 = g_P + ((size_t)(bb + rA) * 512) * 2048;
    const __half* P8 = g_P + ((size_t)(bb + rA + 8) * 512) * 2048;
    __half* hf16 = reinterpret_cast<__half*>(g_hf);

    // pv: {f@rA, u@rA, f@rA8, u@rA8, g@rA, o@rA, g@rA8, o@rA8}
    float pv[8];
    {
        pv[0] = __half2float(__ldg(P0 + hg));
        pv[1] = __half2float(__ldg(P0 + 512 + hg));
        pv[2] = __half2float(__ldg(P8 + hg));
        pv[3] = __half2float(__ldg(P8 + 512 + hg));
        pv[4] = __half2float(__ldg(P0 + 1024 + hg));
        pv[5] = __half2float(__ldg(P0 + 1536 + hg));
        pv[6] = __half2float(__ldg(P8 + 1024 + hg));
        pv[7] = __half2float(__ldg(P8 + 1536 + hg));
    }

    for (int t = 0; t < TT; t++) {
        // ---- stage A frags: h(t) from g_hf (frag order), zeros at t=0 ----
        if (t == 0) {
            uint4 z = make_uint4(0, 0, 0, 0);
            #pragma unroll
            for (int i = 0; i < 4; i++) sA[tid + i * 256] = z;
        } else {
            const uint4* hf = g_hf + ((size_t)(t & 1) * 8 + bgrp) * 1024;
            #pragma unroll
            for (int i = 0; i < 4; i++) sA[tid + i * 256] = ldcg_v4(hf + tid + i * 256);
        }
        __syncthreads();

        // ---- 4 independent accumulator chains, seeded with P(t) ----
        float a0e[4] = {pv[0], pv[1], pv[2], pv[3]};
        float a1e[4] = {pv[4], pv[5], pv[6], pv[7]};
        float a0o[4] = {0.f, 0.f, 0.f, 0.f};
        float a1o[4] = {0.f, 0.f, 0.f, 0.f};

        // ---- GEMM: 16 x 128 x 512, B in registers, pipelined A LDS ----
        uint4 Acur = sA[lane];
        #pragma unroll
        for (int kt = 0; kt < 32; kt++) {
            uint4 Anext;
            if (kt < 31) Anext = sA[(kt + 1) * 32 + lane];
            if (kt & 1) {
                mma16816(a0o, Acur, wb_[kt].x, wb_[kt].y);
                mma16816(a1o, Acur, wb_[kt].z, wb_[kt].w);
            } else {
                mma16816(a0e, Acur, wb_[kt].x, wb_[kt].y);
                mma16816(a1e, Acur, wb_[kt].z, wb_[kt].w);
            }
            Acur = Anext;
        }

        // ---- merge chains + epilogue: 2 cells ----
        {
            float f, u, g, o;
            f = sigf(a0e[0] + a0o[0]); u = sigf(a0e[1] + a0o[1]);
            g = tanh_fast(a1e[0] + a1o[0]); o = sigf(a1e[1] + a1o[1]);
            cs0 = f * cs0 + u * g;  hv0 = o * tanh_fast(cs0);
            f = sigf(a0e[2] + a0o[2]); u = sigf(a0e[3] + a0o[3]);
            g = tanh_fast(a1e[2] + a1o[2]); o = sigf(a1e[3] + a1o[3]);
            cs1 = f * cs1 + u * g;  hv1 = o * tanh_fast(cs1);
        }

        // ---- publish h(t+1) in A-frag order (must precede release) ----
        {
            const int wb2 = (t + 1) & 1;
            const int blk = (wb2 * 8 + bgrp) * 1024;
            size_t i0 = ((size_t)(blk + (hg >> 4) * 32 + rA * 4 + ((hg >> 1) & 3))) * 8
                        + (((hg >> 3) & 1) * 2) * 2 + (hg & 1);
            hf16[i0] = __float2half(hv0);
            hf16[i0 + 2] = __float2half(hv1);
        }

        asm volatile("barrier.cluster.arrive.release.aligned;" ::: "memory");

        // ---- under the barrier wait: out stores + P(t+1) prefetch ----
        out[(size_t)t * (BB * HH) + (size_t)(bb + rA) * HH + hg] = hv0;
        out[(size_t)t * (BB * HH) + (size_t)(bb + rA + 8) * HH + hg] = hv1;
        if (t + 1 < TT) {
            const __half* p0 = P0 + (size_t)(t + 1) * 2048;
            const __half* p8 = P8 + (size_t)(t + 1) * 2048;
            pv[0] = __half2float(__ldg(p0 + hg));
            pv[1] = __half2float(__ldg(p0 + 512 + hg));
            pv[2] = __half2float(__ldg(p8 + hg));
            pv[3] = __half2float(__ldg(p8 + 512 + hg));
            pv[4] = __half2float(__ldg(p0 + 1024 + hg));
            pv[5] = __half2float(__ldg(p0 + 1536 + hg));
            pv[6] = __half2float(__ldg(p8 + 1024 + hg));
            pv[7] = __half2float(__ldg(p8 + 1536 + hg));
        }

        asm volatile("barrier.cluster.wait.acquire.aligned;" ::: "memory");
    }

    // ---- final h, c ----
    {
        const size_t OUT_H = (size_t)TT * BB * HH;
        const size_t OUT_C = OUT_H + (size_t)BB * HH;
        size_t b0 = (size_t)(bb + rA) * HH + hg;
        size_t b1 = (size_t)(bb + rA + 8) * HH + hg;
        out[OUT_H + b0] = hv0;  out[OUT_H + b1] = hv1;
        out[OUT_C + b0] = cs0;  out[OUT_C + b1] = cs1;
    }
}

// ---------------- launcher ----------------

extern "C" void kernel_launch(void* const* d_in, const int* in_sizes, int n_in,
                              void* d_out, int out_size) {
    (void)in_sizes; (void)n_in; (void)out_size;
    const float* x  = (const float*)d_in[0];
    const float* Wf = (const float*)d_in[1];
    const float* bf = (const float*)d_in[2];
    const float* Wu = (const float*)d_in[3];
    const float* bu = (const float*)d_in[4];
    const float* Wc = (const float*)d_in[5];
    const float* bc = (const float*)d_in[6];
    const float* Wo = (const float*)d_in[7];
    const float* bo = (const float*)d_in[8];
    float* out = (float*)d_out;

    cudaFuncSetAttribute(gemm_kernel, cudaFuncAttributeMaxDynamicSharedMemorySize, GM_SMEM);
    cudaFuncSetAttribute(lstm_kernel, cudaFuncAttributeMaxDynamicSharedMemorySize, L_SMEM);
    cudaFuncSetAttribute(lstm_kernel, cudaFuncAttributeNonPortableClusterSizeAllowed, 1);

    pack_kernel<<<640, 256>>>(Wf, Wu, Wc, Wo);
    gemm_kernel<<<dim3(16, 512), 256, GM_SMEM>>>(x, bf, bu, bc, bo);
    lstm_kernel<<<BB, 256, L_SMEM>>>(out);
}